// round 17
// baseline (speedup 1.0000x reference)
#include <cuda_runtime.h>
#include <cuda_fp16.h>
#include <cstdint>

#define BATCH 4
#define SEQ   2048
#define EMB   1024
#define HEADS 16
#define DK    64

// ---------------- device scratch (no cudaMalloc allowed) --------------------
__device__ __half g_qkv_hi[(size_t)BATCH * HEADS * SEQ * DK];
__device__ __half g_att_hi[(size_t)BATCH * SEQ * EMB];
__device__ __half g_w_hi[(size_t)EMB * EMB];

// ---------------- helpers ---------------------------------------------------
__device__ __forceinline__ uint32_t smem_u32(const void* p) {
    uint32_t a;
    asm("{ .reg .u64 t; cvta.to.shared.u64 t, %1; cvt.u32.u64 %0, t; }" : "=r"(a) : "l"(p));
    return a;
}

// 128B rows (64 fp16): 8 chunks of 16B, XOR swizzle -> conflict-free ldmatrix
__device__ __forceinline__ uint32_t swz(uint32_t row, uint32_t chunk) {
    return row * 128u + ((chunk ^ (row & 7u)) * 16u);
}

__device__ __forceinline__ void ldsm4(uint32_t* r, uint32_t addr) {
    asm volatile("ldmatrix.sync.aligned.m8n8.x4.shared.b16 {%0,%1,%2,%3}, [%4];"
        : "=r"(r[0]), "=r"(r[1]), "=r"(r[2]), "=r"(r[3]) : "r"(addr));
}
__device__ __forceinline__ void ldsm4t(uint32_t* r, uint32_t addr) {
    asm volatile("ldmatrix.sync.aligned.m8n8.x4.trans.shared.b16 {%0,%1,%2,%3}, [%4];"
        : "=r"(r[0]), "=r"(r[1]), "=r"(r[2]), "=r"(r[3]) : "r"(addr));
}

// D = A(f16) * B(f16) + D(f32);  m16n8k16 row.col
__device__ __forceinline__ void mma16816(float* c, const uint32_t* a, const uint32_t* b) {
    asm volatile("mma.sync.aligned.m16n8k16.row.col.f32.f16.f16.f32 "
        "{%0,%1,%2,%3}, {%4,%5,%6,%7}, {%8,%9}, {%0,%1,%2,%3};"
        : "+f"(c[0]), "+f"(c[1]), "+f"(c[2]), "+f"(c[3])
        : "r"(a[0]), "r"(a[1]), "r"(a[2]), "r"(a[3]), "r"(b[0]), "r"(b[1]));
}

// async copy 16B global -> shared
__device__ __forceinline__ void cpa16(uint32_t saddr, const void* gaddr) {
    asm volatile("cp.async.cg.shared.global [%0], [%1], 16;" :: "r"(saddr), "l"(gaddr));
}
#define CP_COMMIT() asm volatile("cp.async.commit_group;" ::: "memory")
#define CP_WAIT1()  asm volatile("cp.async.wait_group 1;" ::: "memory")

// exp(s * 0.125) = 2^(s * 0.125*log2(e)) via MUFU EX2: 2 issues, off the FMA pipe.
__device__ __forceinline__ float exp_scaled(float s) {
    float t = s * 0.18033688011f;              // 0.125 * log2(e)
    float r;
    asm("ex2.approx.f32 %0, %1;" : "=f"(r) : "f"(t));
    return r;
}

// pack two floats into one f16x2 word (a -> low half)
__device__ __forceinline__ uint32_t pack2h(float a, float b) {
    __half2 h2 = __floats2half2_rn(a, b);
    return *(uint32_t*)&h2;
}

// ---------------------------------------------------------------------------
// Stage 1: qkv = cos(x + theta) -> single f16 (MUFU __cosf; |arg|<~7)
// ---------------------------------------------------------------------------
__global__ __launch_bounds__(256) void qkv_kernel(const float* __restrict__ x,
                                                  const float* __restrict__ theta) {
    int idx = blockIdx.x * 256 + threadIdx.x;            // over B*S*E
    int e = idx & (EMB - 1);
    int s = (idx >> 10) & (SEQ - 1);
    int b = idx >> 21;
    int h = e >> 6, d = e & (DK - 1);
    float v = __cosf(x[idx] + theta[e]);
    size_t o = ((((size_t)b * HEADS + h) * SEQ) + s) * DK + d;
    g_qkv_hi[o] = __float2half_rn(v);
}

__global__ __launch_bounds__(256) void wsplit_kernel(const float* __restrict__ w) {
    int idx = blockIdx.x * 256 + threadIdx.x;
    g_w_hi[idx] = __float2half_rn(w[idx]);
}

// ---------------------------------------------------------------------------
// Stage 2: attention. CTA = 128 q rows of one (b,h). 8 warps x m16.
// S = Qh @ Kh^T, PV = Ph @ Vh. MUFU exp. 3-stage K ring (prefetch dist 2).
// smem: Q hi [128][64] (16KB) + 3 x 8KB K stages = 40KB; 2 CTAs/SM.
// ---------------------------------------------------------------------------
#define AQ_H 0
#define AKS  16384      // K stages at 16384 + i*8192
#define A_SMEM 40960

__global__ __launch_bounds__(256, 2) void attn_mma() {
    extern __shared__ char smp[];
    const uint32_t sb = smem_u32(smp);
    const int tid = threadIdx.x;
    const int w = tid >> 5, lane = tid & 31;
    const int bid = blockIdx.x;                 // B*H*16
    const int qt = bid & 15, bh = bid >> 4;
    const int b = bh >> 4, h = bh & 15;
    const int q0 = qt * 128;

    const __half* qh_base = g_qkv_hi + (size_t)bh * SEQ * DK;

    // per-thread K-tile slots: 64 rows x 8 chunks = 512 chunks, 2 per thread
    const int lrow0 = tid >> 3,          lc0 = tid & 7;   // rows 0..31
    const int lrow1 = (tid + 256) >> 3,  lc1 = tid & 7;   // rows 32..63
    const uint32_t sw0 = swz(lrow0, lc0), sw1 = swz(lrow1, lc1);

    auto issue_k = [&](int t, uint32_t ss) {
        const __half* gh = qh_base + (size_t)t * 64 * DK;
        cpa16(ss + sw0, gh + (size_t)lrow0 * DK + lc0 * 8);
        cpa16(ss + sw1, gh + (size_t)lrow1 * DK + lc1 * 8);
        CP_COMMIT();
    };

    // prologue: issue K tiles 0 and 1
    issue_k(0, sb + AKS);
    issue_k(1, sb + AKS + 8192);

    // stage Q tile [128][64] (swizzled), overlaps with prologue cp.async
    #pragma unroll
    for (int i = 0; i < 2; i++) {
        int idx = tid + i * 256;
        int row = idx >> 2, c2 = (idx & 3) * 2;       // 2 chunks per slot
        *(uint4*)(smp + AQ_H + swz(row, c2)) =
            *(const uint4*)(qh_base + (size_t)(q0 + row) * DK + c2 * 8);
        *(uint4*)(smp + AQ_H + swz(row, c2 + 1)) =
            *(const uint4*)(qh_base + (size_t)(q0 + row) * DK + c2 * 8 + 8);
    }
    __syncthreads();

    // Q fragments: kk = k16 group (d dim), 4 regs each
    uint32_t qh[4][4];
    #pragma unroll
    for (int kk = 0; kk < 4; kk++)
        ldsm4(qh[kk], sb + AQ_H + swz(16 * w + (lane & 15), 2 * kk + (lane >> 4)));

    float oacc[8][4];
    #pragma unroll
    for (int j = 0; j < 8; j++)
        #pragma unroll
        for (int r = 0; r < 4; r++) oacc[j][r] = 0.0f;
    float den0 = 0.0f, den1 = 0.0f;

    uint32_t stage = 0;
    for (int t = 0; t < 32; t++) {
        const uint32_t kH = sb + AKS + stage * 8192;

        CP_WAIT1();            // tile t resident (t+1 may be in flight)
        __syncthreads();       // all warps done with the stage being refilled

        if (t + 2 < 32) {      // prefetch t+2 into the stage freed by t-1
            uint32_t s2 = stage + 2; if (s2 >= 3) s2 -= 3;
            issue_k(t + 2, sb + AKS + s2 * 8192);
        }

        // ---- S = Qh @ Kh^T ----
        float sacc[8][4];
        #pragma unroll
        for (int j = 0; j < 8; j++)
            #pragma unroll
            for (int r = 0; r < 4; r++) sacc[j][r] = 0.0f;

        #pragma unroll
        for (int kk = 0; kk < 4; kk++) {
            #pragma unroll
            for (int np = 0; np < 4; np++) {
                uint32_t bh4[4];
                uint32_t row = 16 * np + (lane & 15), ch = 2 * kk + (lane >> 4);
                ldsm4(bh4, kH + swz(row, ch));
                uint32_t b0h[2] = { bh4[0], bh4[2] }, b1h[2] = { bh4[1], bh4[3] };
                mma16816(sacc[2 * np],     qh[kk], b0h);
                mma16816(sacc[2 * np + 1], qh[kk], b1h);
            }
        }

        // ---- exp (MUFU) + denominator (no max pass; |S|<=8) ----
        #pragma unroll
        for (int j = 0; j < 8; j++) {
            sacc[j][0] = exp_scaled(sacc[j][0]);
            sacc[j][1] = exp_scaled(sacc[j][1]);
            sacc[j][2] = exp_scaled(sacc[j][2]);
            sacc[j][3] = exp_scaled(sacc[j][3]);
            den0 += sacc[j][0] + sacc[j][1];
            den1 += sacc[j][2] + sacc[j][3];
        }

        // ---- P: pack S accumulators as fp16 A fragments ----
        uint32_t ph[4][4];
        #pragma unroll
        for (int kk = 0; kk < 4; kk++) {
            ph[kk][0] = pack2h(sacc[2 * kk][0],     sacc[2 * kk][1]);
            ph[kk][1] = pack2h(sacc[2 * kk][2],     sacc[2 * kk][3]);
            ph[kk][2] = pack2h(sacc[2 * kk + 1][0], sacc[2 * kk + 1][1]);
            ph[kk][3] = pack2h(sacc[2 * kk + 1][2], sacc[2 * kk + 1][3]);
        }

        // ---- O += Ph @ Vh  (V^T via ldmatrix.trans on the K tile) ----
        #pragma unroll
        for (int kk = 0; kk < 4; kk++) {
            #pragma unroll
            for (int ndp = 0; ndp < 4; ndp++) {
                uint32_t vh4[4];
                uint32_t row = 16 * kk + (lane & 7) + ((lane >> 3) & 1) * 8;
                uint32_t ch  = 2 * ndp + (lane >> 4);
                ldsm4t(vh4, kH + swz(row, ch));
                uint32_t v0h[2] = { vh4[0], vh4[1] }, v1h[2] = { vh4[2], vh4[3] };
                mma16816(oacc[2 * ndp],     ph[kk], v0h);
                mma16816(oacc[2 * ndp + 1], ph[kk], v1h);
            }
        }

        stage = (stage + 1 == 3) ? 0 : stage + 1;
    }

    // denominator: quad-reduce (lanes 4r..4r+3 hold disjoint column subsets)
    den0 += __shfl_xor_sync(0xffffffffu, den0, 1);
    den0 += __shfl_xor_sync(0xffffffffu, den0, 2);
    den1 += __shfl_xor_sync(0xffffffffu, den1, 1);
    den1 += __shfl_xor_sync(0xffffffffu, den1, 2);
    float inv0 = 1.0f / den0, inv1 = 1.0f / den1;

    int r = q0 + 16 * w + (lane >> 2);
    uint32_t* oh1 = (uint32_t*)g_att_hi + ((size_t)b * SEQ + r) * 512 + h * 32 + (lane & 3);
    uint32_t* oh2 = (uint32_t*)g_att_hi + ((size_t)b * SEQ + r + 8) * 512 + h * 32 + (lane & 3);
    #pragma unroll
    for (int nd = 0; nd < 8; nd++) {
        oh1[4 * nd] = pack2h(oacc[nd][0] * inv0, oacc[nd][1] * inv0);
        oh2[4 * nd] = pack2h(oacc[nd][2] * inv1, oacc[nd][3] * inv1);
    }
}

// ---------------------------------------------------------------------------
// Stage 3: out = att @ W^T + bias. CTA tile 128x128, 8 warps (4m x 2n),
// warp tile m32 x n64, K-chunks of 64, single-fp16 A and W.
// 3-stage cp.async pipeline (prefetch distance 2), 32KB/stage = 96KB, 2 CTAs/SM.
// ---------------------------------------------------------------------------
#define OGS_AH 0
#define OGS_BH 16384
#define OG_STAGE 32768
#define OG_SMEM  98304

__global__ __launch_bounds__(256, 2) void gemm_mma(const float* __restrict__ bias,
                                                   float* __restrict__ out) {
    extern __shared__ char smp[];
    const uint32_t sb = smem_u32(smp);
    const int tid = threadIdx.x;
    const int w = tid >> 5, lane = tid & 31;
    const int wy = w >> 1, wx = w & 1;
    const int bm = blockIdx.y * 128, bn = blockIdx.x * 128;

    const __half* Ah = g_att_hi;
    const __half* Bh = g_w_hi;

    float acc[2][8][4];
    #pragma unroll
    for (int mi = 0; mi < 2; mi++)
        #pragma unroll
        for (int j = 0; j < 8; j++)
            #pragma unroll
            for (int rr = 0; rr < 4; rr++) acc[mi][j][rr] = 0.0f;

    // chunk loader: k=64 chunk -> Ah/Bh, 1024 16B-chunks each (128 rows x 8)
    auto issue_chunk = [&](int kc, uint32_t ss) {
        const int kw = kc * 64;
        #pragma unroll
        for (int i = 0; i < 4; i++) {
            int idx = tid + i * 256;          // 1024 slots: 128 rows x 8 chunks
            int row = idx >> 3, c = idx & 7;
            uint32_t sw = swz(row, c);
            cpa16(ss + OGS_AH + sw, Ah + (size_t)(bm + row) * EMB + kw + c * 8);
            cpa16(ss + OGS_BH + sw, Bh + (size_t)(bn + row) * EMB + kw + c * 8);
        }
        CP_COMMIT();
    };

    issue_chunk(0, sb);
    issue_chunk(1, sb + OG_STAGE);

    uint32_t stage = 0;                        // stage index of chunk kc
    for (int kc = 0; kc < 16; kc++) {
        const uint32_t ss = sb + stage * OG_STAGE;

        CP_WAIT1();            // chunk kc resident (kc+1 may be in flight)
        __syncthreads();       // all warps done with the stage being refilled

        if (kc + 2 < 16) {     // prefetch kc+2 into the stage freed by kc-1
            uint32_t stage2 = stage + 2; if (stage2 >= 3) stage2 -= 3;
            issue_chunk(kc + 2, sb + stage2 * OG_STAGE);
        }

        #pragma unroll
        for (int kk = 0; kk < 4; kk++) {
            uint32_t ah0[4], ah1[4];
            uint32_t ch = 2 * kk + (lane >> 4);
            ldsm4(ah0, ss + OGS_AH + swz(32 * wy + (lane & 15),      ch));
            ldsm4(ah1, ss + OGS_AH + swz(32 * wy + 16 + (lane & 15), ch));
            #pragma unroll
            for (int np = 0; np < 4; np++) {
                uint32_t bh4[4];
                uint32_t row = 64 * wx + 16 * np + (lane & 15);
                ldsm4(bh4, ss + OGS_BH + swz(row, ch));
                uint32_t b0h[2] = { bh4[0], bh4[2] }, b1h[2] = { bh4[1], bh4[3] };
                mma16816(acc[0][2 * np],     ah0, b0h);
                mma16816(acc[0][2 * np + 1], ah0, b1h);
                mma16816(acc[1][2 * np],     ah1, b0h);
                mma16816(acc[1][2 * np + 1], ah1, b1h);
            }
        }

        stage = (stage + 1 == 3) ? 0 : stage + 1;
    }

    #pragma unroll
    for (int mi = 0; mi < 2; mi++) {
        int r = bm + 32 * wy + 16 * mi + (lane >> 2);
        #pragma unroll
        for (int nt = 0; nt < 8; nt++) {
            int col = bn + 64 * wx + 8 * nt + 2 * (lane & 3);
            float bv0 = __ldg(bias + col), bv1 = __ldg(bias + col + 1);
            float2 v0, v1;
            v0.x = acc[mi][nt][0] + bv0; v0.y = acc[mi][nt][1] + bv1;
            v1.x = acc[mi][nt][2] + bv0; v1.y = acc[mi][nt][3] + bv1;
            *(float2*)(out + (size_t)r * EMB + col)       = v0;
            *(float2*)(out + (size_t)(r + 8) * EMB + col) = v1;
        }
    }
}

// ---------------------------------------------------------------------------
extern "C" void kernel_launch(void* const* d_in, const int* in_sizes, int n_in,
                              void* d_out, int out_size) {
    const float* x     = (const float*)d_in[0];   // [4,2048,1024]
    const float* theta = (const float*)d_in[1];   // [16,64]
    const float* w_out = (const float*)d_in[2];   // [1024,1024]
    const float* b_out = (const float*)d_in[3];   // [1024]
    float* out = (float*)d_out;                   // [4,2048,1024]

    cudaFuncSetAttribute(attn_mma, cudaFuncAttributeMaxDynamicSharedMemorySize, A_SMEM);
    cudaFuncSetAttribute(gemm_mma, cudaFuncAttributeMaxDynamicSharedMemorySize, OG_SMEM);

    qkv_kernel<<<(BATCH * SEQ * EMB) / 256, 256>>>(x, theta);
    wsplit_kernel<<<(EMB * EMB) / 256, 256>>>(w_out);
    attn_mma<<<BATCH * HEADS * (SEQ / 128), 256, A_SMEM>>>();
    dim3 ggrid(EMB / 128, (BATCH * SEQ) / 128);
    gemm_mma<<<ggrid, 256, OG_SMEM>>>(b_out, out);
}